// round 17
// baseline (speedup 1.0000x reference)
#include <cuda_runtime.h>
#include <cuda_fp16.h>
#include <cstdint>
#include <math.h>

#define BB   4
#define SS   1024
#define DD   512
#define HH   8
#define CC   64
#define MLPD 2048
#define LL   4
#define TOPKK 256
#define D3   (3*DD)

// ---------------- scratch (static device globals) ---------------------------
__device__ float g_x  [BB*SS*DD];                  // residual stream (fp32)
__device__ half  g_ln [BB*SS*DD];                  // fp16 rows (B*S, 512)
__device__ float g_qkv[(size_t)BB*D3*SS];          // (B, 3D, S) fp32
__device__ half  g_q  [BB*HH*SS*CC];               // fp16 rows (B*H*S, 64)
__device__ half  g_k  [BB*HH*SS*CC];
__device__ half  g_v  [BB*HH*CC*SS];               // fp16 transposed rows (B*H*C, 1024)
__device__ half  g_sc [(size_t)BB*HH*SS*SS];       // scores fp16 -> probs fp16 (pitch SS)
__device__ half  g_ao [BB*SS*DD];                  // fp16 rows (B*S, 512)
__device__ half  g_mlp[(size_t)BB*SS*MLPD];        // fp16 rows (B*S, 2048)
__device__ half  c_qkv[(size_t)LL*D3*DD];
__device__ half  c_prj[(size_t)LL*DD*DD];
__device__ half  c_m1 [(size_t)LL*MLPD*DD];
__device__ half  c_m2 [(size_t)LL*DD*MLPD];

// ---------------- helpers ----------------
__device__ __forceinline__ float geluf(float x) {
    return 0.5f * x * (1.0f + erff(x * 0.70710678118654752440f));
}
__device__ __forceinline__ unsigned f2key(float f) {
    unsigned u = __float_as_uint(f);
    return (u & 0x80000000u) ? ~u : (u | 0x80000000u);
}
__device__ __forceinline__ float key2f(unsigned k) {
    unsigned u = (k & 0x80000000u) ? (k & 0x7FFFFFFFu) : ~k;
    return __uint_as_float(u);
}
// fp16 mma: D(f32) += A(16x16 f16, row) * B(16x8 f16, col)
__device__ __forceinline__ void mma_hf(float c[4], const unsigned a[4],
                                       const unsigned b[2]) {
    asm volatile(
        "mma.sync.aligned.m16n8k16.row.col.f32.f16.f16.f32 "
        "{%0,%1,%2,%3}, {%4,%5,%6,%7}, {%8,%9}, {%0,%1,%2,%3};"
        : "+f"(c[0]), "+f"(c[1]), "+f"(c[2]), "+f"(c[3])
        : "r"(a[0]), "r"(a[1]), "r"(a[2]), "r"(a[3]), "r"(b[0]), "r"(b[1]));
}
__device__ __forceinline__ void cp16(unsigned saddr, const void* g) {
    asm volatile("cp.async.cg.shared.global [%0], [%1], 16;\n" :: "r"(saddr), "l"(g));
}
__device__ __forceinline__ void ldm4(unsigned addr, unsigned& r0, unsigned& r1,
                                     unsigned& r2, unsigned& r3) {
    asm volatile("ldmatrix.sync.aligned.m8n8.x4.shared.b16 {%0,%1,%2,%3}, [%4];"
                 : "=r"(r0), "=r"(r1), "=r"(r2), "=r"(r3) : "r"(addr));
}

// ---------------- weight convert: fp32 -> fp16 -------------------------------
__global__ void conv_w(const float* __restrict__ s, half* __restrict__ d, int n) {
    int i = blockIdx.x * 256 + threadIdx.x;
    if (i < n) d[i] = __float2half_rn(s[i]);
}

// ---------------- x = x_in + pos ----------------
__global__ void add_pos_kernel(const float* __restrict__ x,
                               const float* __restrict__ pos,
                               float* __restrict__ out, int total, int per_b) {
    int i = blockIdx.x * blockDim.x + threadIdx.x;
    if (i < total) out[i] = x[i] + pos[i % per_b];
}

// ---------------- layernorm over D=512 --------------------------------------
template <bool HF16OUT>
__global__ void ln_kernel(const float* __restrict__ in,
                          const float* __restrict__ w,
                          const float* __restrict__ b,
                          void* __restrict__ outv) {
    int row = blockIdx.x;
    const float* xr = in + (size_t)row * DD;
    int tid = threadIdx.x;            // 128 threads
    float v[4], s = 0.f, sq = 0.f;
#pragma unroll
    for (int i = 0; i < 4; i++) {
        v[i] = xr[tid + i * 128];
        s += v[i]; sq += v[i] * v[i];
    }
    __shared__ float rs[32], rq[32];
#pragma unroll
    for (int o = 16; o; o >>= 1) {
        s  += __shfl_down_sync(0xFFFFFFFFu, s,  o);
        sq += __shfl_down_sync(0xFFFFFFFFu, sq, o);
    }
    int warp = tid >> 5, lane = tid & 31;
    if (lane == 0) { rs[warp] = s; rq[warp] = sq; }
    __syncthreads();
    float a4 = rs[0] + rs[1] + rs[2] + rs[3];
    float c4 = rq[0] + rq[1] + rq[2] + rq[3];
    float mu   = a4 * (1.0f / DD);
    float var  = c4 * (1.0f / DD) - mu * mu;
    float rstd = rsqrtf(var + 1e-6f);
    if (HF16OUT) {
        half* yr = (half*)outv + (size_t)row * DD;
#pragma unroll
        for (int i = 0; i < 4; i++) {
            int d = tid + i * 128;
            yr[d] = __float2half_rn((v[i] - mu) * rstd * w[d] + b[d]);
        }
    } else {
        float* yr = (float*)outv + (size_t)row * DD;
#pragma unroll
        for (int i = 0; i < 4; i++) {
            int d = tid + i * 128;
            yr[d] = (v[i] - mu) * rstd * w[d] + b[d];
        }
    }
}

// =================== pipelined single-pass fp16 tensor-core GEMM =============
// C(r,q) = sum_k X(r,k)*W(q,k); X rows at X + r*ldx, W rows at W + q*ldw.
// Block tile: 128(r) x QT(q), BK=64.  8 warps. fp32 accum.
// OUT_MODE: 0 = float Y (TRANS_OUT/RESID per flags)
//           1 = attn-out: fp16 into (B,S,D) rows (z = b*8+h)
//           2 = fp16 rows, pitch M, z-stride ys (scores / mlp1)
template <int QT, int OUT_MODE, bool TRANS_OUT, bool GELU_ACT, bool RESID>
__global__ void __launch_bounds__(256)
gemm_hf(const half* __restrict__ Xb, const half* __restrict__ Wb,
        const float* __restrict__ bias, void* __restrict__ Yv,
        int N, int M, int K, int ldx, int ldw, long xs, long ws, long ys) {
    constexpr int BK  = 64;
    constexpr int LDBY = 144;                // smem row stride: 128B data + 16B pad
    constexpr int XBYTES = 128 * LDBY;       // 18432
    constexpr int WBYTES = QT * LDBY;
    constexpr int STAGE  = XBYTES + WBYTES;
    constexpr int RW = (QT == 128) ? 64 : 32;
    constexpr int RTILES = RW / 16;

    extern __shared__ char smem_raw[];
    const unsigned sbase = (unsigned)__cvta_generic_to_shared(smem_raw);

    const half* X = Xb + (size_t)blockIdx.z * xs;
    const half* W = Wb + (size_t)blockIdx.z * ws;

    const int tid  = threadIdx.x;
    const int lane = tid & 31, warp = tid >> 5;
    const int wr = (QT == 128) ? (warp >> 2) : (warp >> 1);
    const int wq = (QT == 128) ? (warp & 3)  : (warp & 1);
    const int r_base = wr * RW, q_base = wq * 32;
    const int gr = lane >> 2, gc = lane & 3;
    const int lane15 = lane & 15;
    const int hi8 = (lane >> 4) & 1;

    const int q0 = blockIdx.x * QT, n0 = blockIdx.y * 128;
    const int nk = K / BK;

    const unsigned aOff = (unsigned)((r_base + lane15) * LDBY + hi8 * 16);
    const unsigned bOff = (unsigned)(XBYTES + (q_base + lane15) * LDBY + hi8 * 16);

    float acc[RTILES][4][4];
#pragma unroll
    for (int i = 0; i < RTILES; i++)
#pragma unroll
        for (int j = 0; j < 4; j++)
#pragma unroll
            for (int t = 0; t < 4; t++) acc[i][j][t] = 0.f;

    auto stage = [&](int it, int buf) {
        const int k0 = it * BK;
        const unsigned sb = sbase + buf * STAGE;
#pragma unroll
        for (int u = 0; u < 4; u++) {                 // X: 1024 16B-chunks
            int c = tid + u * 256;
            int row = c >> 3, col = c & 7;
            cp16(sb + row * LDBY + col * 16,
                 X + (size_t)(n0 + row) * ldx + k0 + col * 8);
        }
#pragma unroll
        for (int u = 0; u < QT / 32; u++) {           // W: QT*8 chunks
            int c = tid + u * 256;
            int row = c >> 3, col = c & 7;
            cp16(sb + XBYTES + row * LDBY + col * 16,
                 W + (size_t)(q0 + row) * ldw + k0 + col * 8);
        }
        asm volatile("cp.async.commit_group;\n" ::);
    };

    stage(0, 0);
    for (int it = 0; it < nk; it++) {
        if (it + 1 < nk) {
            stage(it + 1, (it + 1) & 1);
            asm volatile("cp.async.wait_group 1;\n" ::);
        } else {
            asm volatile("cp.async.wait_group 0;\n" ::);
        }
        __syncthreads();
        const unsigned sb = sbase + (it & 1) * STAGE;
        const unsigned aH0 = sb + aOff;
        const unsigned bH0 = sb + bOff;
#pragma unroll
        for (int ks = 0; ks < BK; ks += 16) {
            unsigned a[RTILES][4];
#pragma unroll
            for (int i = 0; i < RTILES; i++) {
                ldm4(aH0 + i * (16 * LDBY) + ks * 2,
                     a[i][0], a[i][1], a[i][2], a[i][3]);
            }
#pragma unroll
            for (int jp = 0; jp < 2; jp++) {
                unsigned bb[4];
                ldm4(bH0 + jp * (16 * LDBY) + ks * 2, bb[0], bb[1], bb[2], bb[3]);
#pragma unroll
                for (int jj = 0; jj < 2; jj++) {
                    const int j = 2 * jp + jj;
                    unsigned bf[2] = { bb[jj], bb[2 + jj] };
#pragma unroll
                    for (int i = 0; i < RTILES; i++) mma_hf(acc[i][j], a[i], bf);
                }
            }
        }
        __syncthreads();
    }

    // ---- epilogue ----
#pragma unroll
    for (int i = 0; i < RTILES; i++) {
#pragma unroll
        for (int j = 0; j < 4; j++) {
#pragma unroll
            for (int t = 0; t < 4; t++) {
                int r = n0 + r_base + i * 16 + gr + ((t >= 2) ? 8 : 0);
                int q = q0 + q_base + j * 8 + 2 * gc + (t & 1);
                float v = acc[i][j][t];
                if (bias) v += bias[q];
                if (GELU_ACT) v = geluf(v);
                if (OUT_MODE == 0) {
                    float* Y = (float*)Yv + (size_t)blockIdx.z * ys;
                    size_t idx = TRANS_OUT ? ((size_t)q * N + r) : ((size_t)r * M + q);
                    if (RESID) Y[idx] += v; else Y[idx] = v;
                } else if (OUT_MODE == 1) {
                    half* Y = (half*)Yv;
                    int b = blockIdx.z >> 3, h = blockIdx.z & 7;
                    Y[((size_t)(b * SS + r)) * DD + h * CC + q] = __float2half_rn(v);
                } else {
                    half* Y = (half*)Yv + (size_t)blockIdx.z * ys;
                    Y[(size_t)r * M + q] = __float2half_rn(v);
                }
            }
        }
    }
}

// ------- depthwise conv3 + head split + (q,k) L2-normalize -------------------
__global__ void conv_heads(const float* __restrict__ qkv,
                           const float* __restrict__ dw,  // (3D, 3)
                           half* __restrict__ q,
                           half* __restrict__ k,
                           half* __restrict__ v) {
    int b = blockIdx.z;
    int part = blockIdx.y / HH, h = blockIdx.y % HH;
    int s0 = blockIdx.x * 64;
    int ch0 = part * DD + h * CC;
    __shared__ float tin[64][66];
    __shared__ float ct[64][65];
    int tid = threadIdx.x;

    for (int idx = tid; idx < 64 * 66; idx += 256) {
        int c = idx / 66, j = idx % 66;
        int s = s0 + j - 1;
        float val = 0.f;
        if (s >= 0 && s < SS) val = qkv[((size_t)b * D3 + ch0 + c) * SS + s];
        tin[c][j] = val;
    }
    __syncthreads();
    for (int idx = tid; idx < 4096; idx += 256) {
        int c = idx >> 6, s = idx & 63;
        const float* wp = dw + (ch0 + c) * 3;
        ct[c][s] = wp[0] * tin[c][s] + wp[1] * tin[c][s + 1] + wp[2] * tin[c][s + 2];
    }
    __syncthreads();
    if (part == 2) {
        half* outv = v + ((size_t)(b * HH + h) * CC) * SS;
        for (int idx = tid; idx < 4096; idx += 256) {
            int s = idx >> 6, c = idx & 63;
            outv[(size_t)c * SS + s0 + s] = __float2half_rn(ct[c][s]);
        }
    } else {
        __shared__ float red[4][64];
        __shared__ float rnorm[64];
        int tx = tid & 63, ty = tid >> 6;
        float p = 0.f;
        for (int c = ty * 16; c < ty * 16 + 16; c++) {
            float u = ct[c][tx];
            p += u * u;
        }
        red[ty][tx] = p;
        __syncthreads();
        if (ty == 0) {
            float nn = red[0][tx] + red[1][tx] + red[2][tx] + red[3][tx];
            rnorm[tx] = 1.f / fmaxf(sqrtf(nn), 1e-12f);
        }
        __syncthreads();
        half* out = (part == 0 ? q : k) + ((size_t)(b * HH + h) * SS + s0) * CC;
        for (int idx = tid; idx < 4096; idx += 256) {
            int s = idx >> 6, c = idx & 63;
            out[s * CC + c] = __float2half_rn(ct[c][s] * rnorm[s]);
        }
    }
}

// ------- top-k (exact radix select) + masked softmax -------------------------
// Barrier-light. Reads fp16 scores row (pitch SS); selection is exact over the
// fp16-rounded values. Writes probs fp16 in place.
__global__ void topk_softmax(half* __restrict__ scores,
                             const float* __restrict__ temp) {
    int bh = blockIdx.y;
    int h = bh % HH;
    int s = blockIdx.x;
    half* row = scores + ((size_t)bh * SS + s) * SS;
    float t = temp[h];
    __shared__ unsigned keys[SS];
    __shared__ unsigned hist[256];
    __shared__ float fred[8];
    __shared__ unsigned sh_prefix;
    __shared__ int sh_k;
    int tid = threadIdx.x;
    int lane = tid & 31, warp = tid >> 5;

    float lmax = -3.4e38f;
#pragma unroll
    for (int i = 0; i < 4; i++) {
        int idx = tid + i * 256;
        float f = __half2float(row[idx]) * t;
        keys[idx] = f2key(f);
        lmax = fmaxf(lmax, f);
    }
#pragma unroll
    for (int o = 16; o; o >>= 1)
        lmax = fmaxf(lmax, __shfl_xor_sync(0xFFFFFFFFu, lmax, o));
    if (lane == 0) fred[warp] = lmax;
    hist[tid] = 0u;
    if (tid == 0) { sh_prefix = 0u; sh_k = TOPKK; }
    __syncthreads();                                    // (1)
    float maxv = fred[0];
#pragma unroll
    for (int i = 1; i < 8; i++) maxv = fmaxf(maxv, fred[i]);

    for (int pass = 0; pass < 4; pass++) {
        int shift = 24 - 8 * pass;
        unsigned pref = sh_prefix;
        unsigned mask = (pass == 0) ? 0u : (0xFFFFFFFFu << (shift + 8));
#pragma unroll
        for (int i = 0; i < 4; i++) {
            unsigned key = keys[tid + i * 256];
            if ((key & mask) == pref) atomicAdd(&hist[(key >> shift) & 255], 1u);
        }
        __syncthreads();                                // (2) hist complete
        if (warp == 0) {
            int kk = sh_k;
            unsigned hh[8];
#pragma unroll
            for (int j = 0; j < 8; j++) {
                hh[j] = hist[lane * 8 + j];
                hist[lane * 8 + j] = 0u;                // re-zero for next pass
            }
            unsigned sfx[8];                            // suffix within lane
            sfx[7] = hh[7];
#pragma unroll
            for (int j = 6; j >= 0; j--) sfx[j] = hh[j] + sfx[j + 1];
            unsigned run = sfx[0];
#pragma unroll
            for (int o = 1; o < 32; o <<= 1) {
                unsigned v = __shfl_down_sync(0xFFFFFFFFu, run, o);
                if (lane + o < 32) run += v;
            }
            unsigned above = run - sfx[0];              // sum over lanes > lane
#pragma unroll
            for (int j = 0; j < 8; j++) {
                int sfxb = (int)(above + sfx[j]);
                int nxt  = (j < 7) ? (int)(above + sfx[j + 1]) : (int)above;
                if (sfxb >= kk && nxt < kk) {
                    sh_prefix = pref | ((unsigned)(lane * 8 + j) << shift);
                    sh_k = kk - nxt;
                }
            }
        }
        __syncthreads();                                // (3) publish prefix
    }
    float vstar = key2f(sh_prefix);
    float m = fminf(fmaxf(maxv, -10000.f), 10000.f);

    float lsum = 0.f;
#pragma unroll
    for (int i = 0; i < 4; i++) {
        int idx = tid + i * 256;
        float f = key2f(keys[idx]);
        float p = (f >= vstar) ? fminf(fmaxf(f, -10000.f), 10000.f) : -10000.f;
        float e = expf(p - m);
        ((float*)keys)[idx] = e;
        lsum += e;
    }
#pragma unroll
    for (int o = 16; o; o >>= 1)
        lsum += __shfl_xor_sync(0xFFFFFFFFu, lsum, o);
    if (lane == 0) fred[warp] = lsum;
    __syncthreads();                                    // (4)
    float tsum = fred[0];
#pragma unroll
    for (int i = 1; i < 8; i++) tsum += fred[i];
    float inv = 1.f / tsum;
#pragma unroll
    for (int i = 0; i < 4; i++) {
        int idx = tid + i * 256;
        row[idx] = __float2half_rn(((float*)keys)[idx] * inv);
    }
}

// ---------------- host orchestration ----------------------------------------
extern "C" void kernel_launch(void* const* d_in, const int* in_sizes, int n_in,
                              void* d_out, int out_size) {
    (void)in_sizes; (void)n_in; (void)out_size;
    const float* x      = (const float*)d_in[0];
    const float* pos    = (const float*)d_in[1];
    const float* ln1_w  = (const float*)d_in[2];
    const float* ln1_b  = (const float*)d_in[3];
    const float* qkv_w  = (const float*)d_in[4];
    const float* dw_w   = (const float*)d_in[5];
    const float* temp   = (const float*)d_in[6];
    const float* proj_w = (const float*)d_in[7];
    const float* ln2_w  = (const float*)d_in[8];
    const float* ln2_b  = (const float*)d_in[9];
    const float* mlp_w1 = (const float*)d_in[10];
    const float* mlp_b1 = (const float*)d_in[11];
    const float* mlp_w2 = (const float*)d_in[12];
    const float* mlp_b2 = (const float*)d_in[13];
    const float* lnf_w  = (const float*)d_in[14];
    const float* lnf_b  = (const float*)d_in[15];
    float* out = (float*)d_out;

    float *gx, *gqkv;
    half *gln, *gq, *gk, *gv, *gsc, *gao, *gmlp;
    half *cqkv, *cprj, *cm1, *cm2;
    cudaGetSymbolAddress((void**)&gx,   g_x);
    cudaGetSymbolAddress((void**)&gln,  g_ln);
    cudaGetSymbolAddress((void**)&gqkv, g_qkv);
    cudaGetSymbolAddress((void**)&gq,   g_q);
    cudaGetSymbolAddress((void**)&gk,   g_k);
    cudaGetSymbolAddress((void**)&gv,   g_v);
    cudaGetSymbolAddress((void**)&gsc,  g_sc);
    cudaGetSymbolAddress((void**)&gao,  g_ao);
    cudaGetSymbolAddress((void**)&gmlp, g_mlp);
    cudaGetSymbolAddress((void**)&cqkv, c_qkv);
    cudaGetSymbolAddress((void**)&cprj, c_prj);
    cudaGetSymbolAddress((void**)&cm1,  c_m1);
    cudaGetSymbolAddress((void**)&cm2,  c_m2);

    const int SM128 = (128 * 144 + 128 * 144) * 2;   // 73728
    const int SM64  = (128 * 144 + 64 * 144) * 2;    // 55296
    cudaFuncSetAttribute(gemm_hf<128, 0, true,  false, false>,
                         cudaFuncAttributeMaxDynamicSharedMemorySize, SM128);
    cudaFuncSetAttribute(gemm_hf<128, 2, false, false, false>,
                         cudaFuncAttributeMaxDynamicSharedMemorySize, SM128);
    cudaFuncSetAttribute(gemm_hf<64,  0, false, false, true>,
                         cudaFuncAttributeMaxDynamicSharedMemorySize, SM64);
    cudaFuncSetAttribute(gemm_hf<128, 2, false, true,  false>,
                         cudaFuncAttributeMaxDynamicSharedMemorySize, SM128);
    cudaFuncSetAttribute(gemm_hf<64,  1, false, false, false>,
                         cudaFuncAttributeMaxDynamicSharedMemorySize, SM64);

    {
        int n;
        n = LL * D3 * DD;
        conv_w<<<(n + 255) / 256, 256>>>(qkv_w,  cqkv, n);
        n = LL * DD * DD;
        conv_w<<<(n + 255) / 256, 256>>>(proj_w, cprj, n);
        n = LL * MLPD * DD;
        conv_w<<<(n + 255) / 256, 256>>>(mlp_w1, cm1, n);
        n = LL * DD * MLPD;
        conv_w<<<(n + 255) / 256, 256>>>(mlp_w2, cm2, n);
    }

    const int NBS = BB * SS;
    add_pos_kernel<<<(BB * SS * DD + 255) / 256, 256>>>(x, pos, gx,
                                                        BB * SS * DD, SS * DD);

    for (int l = 0; l < LL; l++) {
        ln_kernel<true><<<NBS, 128>>>(gx, ln1_w + l * DD, ln1_b + l * DD, gln);
        // qkv: per batch (1536 x 512) @ (512 x 1024)^T -> (B, 3D, S) fp32
        gemm_hf<128, 0, true, false, false>
            <<<dim3(D3 / 128, SS / 128, BB), 256, SM128>>>(
            gln, cqkv + (size_t)l * D3 * DD, nullptr, gqkv,
            SS, D3, DD, DD, DD, (long)SS * DD, 0, (long)D3 * SS);
        // depthwise conv3 + head split + q/k normalize (fp16 out)
        conv_heads<<<dim3(SS / 64, 3 * HH, BB), 256>>>(
            gqkv, dw_w + (size_t)l * D3 * 3, gq, gk, gv);
        // scores = q k^T (K=64) -> fp16 rows pitch SS
        gemm_hf<128, 2, false, false, false>
            <<<dim3(SS / 128, SS / 128, BB * HH), 256, SM128>>>(
            gq, gk, nullptr, gsc, SS, SS, CC,
            CC, CC, (long)SS * CC, (long)SS * CC, (long)SS * SS);
        // top-k + masked softmax -> probs fp16 (in place, pitch SS)
        topk_softmax<<<dim3(SS, BB * HH), 256>>>(gsc, temp + l * HH);
        // attn @ V -> gao fp16 in (B,S,D)
        gemm_hf<64, 1, false, false, false>
            <<<dim3(1, SS / 128, BB * HH), 256, SM64>>>(
            gsc, gv, nullptr, gao, SS, CC, SS,
            SS, SS, (long)SS * SS, (long)CC * SS, 0);
        // proj + residual into x (fp32), QT=64 -> 256 CTAs
        gemm_hf<64, 0, false, false, true>
            <<<dim3(DD / 64, NBS / 128, 1), 256, SM64>>>(
            gao, cprj + (size_t)l * DD * DD, nullptr, gx,
            NBS, DD, DD, DD, DD, 0, 0, 0);
        ln_kernel<true><<<NBS, 128>>>(gx, ln2_w + l * DD, ln2_b + l * DD, gln);
        // mlp fc1 + gelu -> gmlp fp16
        gemm_hf<128, 2, false, true, false>
            <<<dim3(MLPD / 128, NBS / 128, 1), 256, SM128>>>(
            gln, cm1 + (size_t)l * MLPD * DD, mlp_b1 + l * MLPD, gmlp,
            NBS, MLPD, DD, DD, DD, 0, 0, 0);
        // mlp fc2 + bias + residual into x (fp32), QT=64 -> 256 CTAs
        gemm_hf<64, 0, false, false, true>
            <<<dim3(DD / 64, NBS / 128, 1), 256, SM64>>>(
            gmlp, cm2 + (size_t)l * DD * MLPD, mlp_b2 + l * DD, gx,
            NBS, DD, MLPD, MLPD, MLPD, 0, 0, 0);
    }
    ln_kernel<false><<<NBS, 128>>>(gx, lnf_w, lnf_b, out);
}